// round 4
// baseline (speedup 1.0000x reference)
#include <cuda_runtime.h>

// MS-SSIM-like score, 3 window sizes (5, 11, 17), fused separable implementation.
// out = 0.25 + sum_k clip(ssim_k, -1, 1) / 12   (algebraic collapse of reference)

#define TILE 32
#define RAD 8           // max radius (k=17)
#define S 48            // TILE + 2*RAD
#define NTHREADS 256
#define SSIM_C1 (0.01f*0.01f)
#define SSIM_C2 (0.03f*0.03f)

__constant__ float c_g5[25];
__constant__ float c_g11[121];
__constant__ float c_g17[289];

// Process one window size: horizontal separable pass into H, then vertical pass
// with 4-row register blocking + SSIM epilogue accumulated into acc[4].
template<int R>
__device__ __forceinline__ void window_pass(
    const float* __restrict__ cg,   // 2D filter [K,K], row-major (channel-0 slice)
    const float* __restrict__ s1,
    const float* __restrict__ s2,
    float* __restrict__ H,          // 5 planes of [48][32]
    int tid, float acc[4])
{
    constexpr int K = 2*R + 1;

    // ---- horizontal pass: rows 0..47, output cols 0..31 (tile x 8..39) ----
    #pragma unroll
    for (int sIt = 0; sIt < 6; ++sIt) {
        int i = tid + NTHREADS * sIt;          // 0..1535
        int row = i >> 5;
        int c   = i & 31;
        int xx  = c + RAD;
        float mu1 = 0.f, mu2 = 0.f, m11 = 0.f, m22 = 0.f, m12 = 0.f;
        #pragma unroll
        for (int t = 0; t < K; ++t) {
            float w  = cg[R*K + t];            // center row = horizontal 1D factor
            float v1 = s1[row*S + xx - R + t];
            float v2 = s2[row*S + xx - R + t];
            float wv1 = w * v1;
            float wv2 = w * v2;
            mu1 += wv1;
            mu2 += wv2;
            m11 = fmaf(wv1, v1, m11);
            m22 = fmaf(wv2, v2, m22);
            m12 = fmaf(wv1, v2, m12);
        }
        int o = row*32 + c;
        H[o]           = mu1;
        H[1536   + o]  = mu2;
        H[2*1536 + o]  = m11;
        H[3*1536 + o]  = m22;
        H[4*1536 + o]  = m12;
    }
    __syncthreads();

    // ---- vertical pass: each thread handles 4 consecutive output rows ----
    const int col = tid & 31;
    const int ty  = tid >> 5;                  // 0..7 -> output rows 4*ty .. 4*ty+3
    float a0[4] = {0,0,0,0}, a1[4] = {0,0,0,0}, a2[4] = {0,0,0,0};
    float a3[4] = {0,0,0,0}, a4[4] = {0,0,0,0};
    const int ybase = RAD + 4*ty - R;
    #pragma unroll
    for (int yy0 = 0; yy0 < 4 + 2*R; ++yy0) {
        int o = (ybase + yy0)*32 + col;
        float h0 = H[o];
        float h1 = H[1536   + o];
        float h2 = H[2*1536 + o];
        float h3 = H[3*1536 + o];
        float h4 = H[4*1536 + o];
        #pragma unroll
        for (int j = 0; j < 4; ++j) {
            int t = yy0 - j;                   // compile-time resolvable
            if (t >= 0 && t <= 2*R) {
                float w = cg[t*K + R];         // center column (unnormalized)
                a0[j] = fmaf(w, h0, a0[j]);
                a1[j] = fmaf(w, h1, a1[j]);
                a2[j] = fmaf(w, h2, a2[j]);
                a3[j] = fmaf(w, h3, a3[j]);
                a4[j] = fmaf(w, h4, a4[j]);
            }
        }
    }

    // normalization of column factor folded into one post-scale
    float inv_c = 1.0f / cg[R*K + R];
    #pragma unroll
    for (int j = 0; j < 4; ++j) {
        float mu1 = a0[j] * inv_c;
        float mu2 = a1[j] * inv_c;
        float m11 = a2[j] * inv_c;
        float m22 = a3[j] * inv_c;
        float m12 = a4[j] * inv_c;
        float mu1sq = mu1 * mu1;
        float mu2sq = mu2 * mu2;
        float mu12  = mu1 * mu2;
        float s1sq = fabsf(m11 - mu1sq);
        float s2sq = fabsf(m22 - mu2sq);
        float s12  = m12 - mu12;
        float num = (2.f*mu12 + SSIM_C1) * (2.f*s12 + SSIM_C2);
        float den = (mu1sq + mu2sq + SSIM_C1) * (s1sq + s2sq + SSIM_C2);
        float v = __fdividef(num, den);
        v = fminf(1.f, fmaxf(-1.f, v));
        acc[j] += v;
    }
    __syncthreads();   // protect H before next window overwrites it
}

__global__ __launch_bounds__(NTHREADS)
void mssim_kernel(const float* __restrict__ b1,
                  const float* __restrict__ b2,
                  float* __restrict__ out)
{
    __shared__ float sm[12288];                // 48KB: s1(2304) s2(2304) H(7680)
    float* s1 = sm;
    float* s2 = sm + 2304;
    float* H  = sm + 4608;

    const int tid = threadIdx.x;
    const int plane = blockIdx.z;              // b*C + c, 0..95
    const long base = (long)plane * (512*512);
    const int ox = blockIdx.x * TILE - RAD;
    const int oy = blockIdx.y * TILE - RAD;

    // load 48x48 tiles of b1, b2 with zero padding
    #pragma unroll
    for (int sIt = 0; sIt < 9; ++sIt) {
        int i  = tid + NTHREADS * sIt;         // 0..2303
        int ly = i / S;
        int lx = i - ly * S;
        int gy = oy + ly;
        int gx = ox + lx;
        float v1 = 0.f, v2 = 0.f;
        if (gy >= 0 && gy < 512 && gx >= 0 && gx < 512) {
            long idx = base + (long)gy*512 + gx;
            v1 = b1[idx];
            v2 = b2[idx];
        }
        s1[i] = v1;
        s2[i] = v2;
    }
    __syncthreads();

    float acc[4] = {0.f, 0.f, 0.f, 0.f};
    window_pass<2>(c_g5,  s1, s2, H, tid, acc);
    window_pass<5>(c_g11, s1, s2, H, tid, acc);
    window_pass<8>(c_g17, s1, s2, H, tid, acc);

    const int tx = tid & 31;
    const int ty = tid >> 5;
    const int gx = blockIdx.x * TILE + tx;
    #pragma unroll
    for (int j = 0; j < 4; ++j) {
        int gy = blockIdx.y * TILE + ty*4 + j;
        out[base + (long)gy*512 + gx] = 0.25f + acc[j] * (1.0f/12.0f);
    }
}

extern "C" void kernel_launch(void* const* d_in, const int* in_sizes, int n_in,
                              void* d_out, int out_size) {
    const float* b1 = (const float*)d_in[0];
    const float* b2 = (const float*)d_in[1];
    // filters are [C=3,1,k,k] with identical channel slices; copy channel 0 only
    cudaMemcpyToSymbolAsync(c_g5,  d_in[2],  25*sizeof(float), 0, cudaMemcpyDeviceToDevice, 0);
    cudaMemcpyToSymbolAsync(c_g11, d_in[3], 121*sizeof(float), 0, cudaMemcpyDeviceToDevice, 0);
    cudaMemcpyToSymbolAsync(c_g17, d_in[4], 289*sizeof(float), 0, cudaMemcpyDeviceToDevice, 0);

    dim3 grid(512/TILE, 512/TILE, 96);         // 16 x 16 x (B*C)
    mssim_kernel<<<grid, NTHREADS>>>(b1, b2, (float*)d_out);
}

// round 7
// speedup vs baseline: 1.2306x; 1.2306x over previous
#include <cuda_runtime.h>

// MS-SSIM (windows 5/11/17), fused separable, f32x2-packed implementation.
// out = 0.25 + sum_k clip(ssim_k, -1, 1) / 12

#define TILE 32
#define RAD 8
#define S 48
#define NT 256
#define SSIM_C1 (0.01f*0.01f)
#define SSIM_C2 (0.03f*0.03f)

struct Weights {
    float2 h5[5],  v5[5];     // horizontal: raw center row (dup pairs)
    float2 h11[11], v11[11];  // vertical:   center col / center (dup pairs)
    float2 h17[17], v17[17];
};
__device__  Weights g_stage;
__constant__ Weights c_w;

union F2U { float2 f; unsigned long long u; };

__device__ __forceinline__ float2 ffma2(float2 a, float2 b, float2 c) {
    F2U A, B, C, D; A.f = a; B.f = b; C.f = c;
    asm("fma.rn.f32x2 %0, %1, %2, %3;" : "=l"(D.u) : "l"(A.u), "l"(B.u), "l"(C.u));
    return D.f;
}
__device__ __forceinline__ float2 fmul2(float2 a, float2 b) {
    F2U A, B, D; A.f = a; B.f = b;
    asm("mul.rn.f32x2 %0, %1, %2;" : "=l"(D.u) : "l"(A.u), "l"(B.u));
    return D.f;
}

// ---- prep: build packed 1D factors from the 2D filters (channel-0 slice) ----
__global__ void prep_weights(const float* g5, const float* g11, const float* g17) {
    if (threadIdx.x != 0) return;
    #pragma unroll
    for (int t = 0; t < 5; ++t) {
        float h = g5[2*5 + t];
        float v = g5[t*5 + 2] / g5[2*5 + 2];
        g_stage.h5[t] = make_float2(h, h);
        g_stage.v5[t] = make_float2(v, v);
    }
    #pragma unroll
    for (int t = 0; t < 11; ++t) {
        float h = g11[5*11 + t];
        float v = g11[t*11 + 5] / g11[5*11 + 5];
        g_stage.h11[t] = make_float2(h, h);
        g_stage.v11[t] = make_float2(v, v);
    }
    #pragma unroll
    for (int t = 0; t < 17; ++t) {
        float h = g17[8*17 + t];
        float v = g17[t*17 + 8] / g17[8*17 + 8];
        g_stage.h17[t] = make_float2(h, h);
        g_stage.v17[t] = make_float2(v, v);
    }
}

// ---- one window: packed horizontal pass into H planes, vertical + epilogue ----
template<int R>
__device__ __forceinline__ void wpass(const float2* __restrict__ sT,
                                      float2* __restrict__ Hmu,
                                      float2* __restrict__ Hm,
                                      float*  __restrict__ Hc,
                                      int tid, float acc[4])
{
    constexpr int K = 2*R + 1;
    const float2* wh = (R == 2) ? c_w.h5 : (R == 5) ? c_w.h11 : c_w.h17;
    const float2* wv = (R == 2) ? c_w.v5 : (R == 5) ? c_w.v11 : c_w.v17;

    // horizontal: 768 column-pairs (48 rows x 16 pairs), 3 per thread.
    // sliding loads: column pair shares K+1 LDS.64 of interleaved (v1,v2).
    #pragma unroll
    for (int it = 0; it < 3; ++it) {
        int i   = tid + NT * it;
        int row = i >> 4;
        int cg  = i & 15;                    // cols (2cg, 2cg+1)
        int sbase = row * S + 2*cg + RAD - R;
        float2 mu0 = {0,0}, mu1 = {0,0}, mm0 = {0,0}, mm1 = {0,0};
        float  c0 = 0.f, c1 = 0.f;
        #pragma unroll
        for (int s = 0; s < K + 1; ++s) {
            float2 v = sT[sbase + s];        // LDS.64: (v1, v2)
            if (s < K) {                     // col 0, tap s
                float2 wp = wh[s];
                mu0 = ffma2(wp, v, mu0);
                float2 wvp = fmul2(wp, v);
                mm0 = ffma2(wvp, v, mm0);
                c0  = fmaf(wvp.x, v.y, c0);
            }
            if (s >= 1) {                    // col 1, tap s-1
                float2 wp = wh[s-1];
                mu1 = ffma2(wp, v, mu1);
                float2 wvp = fmul2(wp, v);
                mm1 = ffma2(wvp, v, mm1);
                c1  = fmaf(wvp.x, v.y, c1);
            }
        }
        int o = row * 32 + 2*cg;
        Hmu[o] = mu0; Hmu[o+1] = mu1;
        Hm[o]  = mm0; Hm[o+1]  = mm1;
        Hc[o]  = c0;  Hc[o+1]  = c1;
    }
    __syncthreads();

    // vertical: 1 col x 4 rows per thread, packed quantity lanes
    const int col = tid & 31;
    const int ty  = tid >> 5;
    float2 amu[4] = {}; float2 am[4] = {}; float ac[4] = {0,0,0,0};
    const int ybase = RAD + 4*ty - R;
    #pragma unroll
    for (int yy = 0; yy < 4 + 2*R; ++yy) {
        int o = (ybase + yy) * 32 + col;
        float2 hmu = Hmu[o];
        float2 hm  = Hm[o];
        float  hc  = Hc[o];
        #pragma unroll
        for (int j = 0; j < 4; ++j) {
            int t = yy - j;
            if (t >= 0 && t < K) {
                float2 wp = wv[t];
                amu[j] = ffma2(wp, hmu, amu[j]);
                am[j]  = ffma2(wp, hm,  am[j]);
                ac[j]  = fmaf(wp.x, hc, ac[j]);
            }
        }
    }

    // epilogue (normalization already folded into vertical weights)
    #pragma unroll
    for (int j = 0; j < 4; ++j) {
        float mu1_ = amu[j].x, mu2_ = amu[j].y;
        float m11  = am[j].x,  m22  = am[j].y, m12 = ac[j];
        float2 musq2 = fmul2(amu[j], amu[j]);       // (mu1^2, mu2^2)
        float mu1sq = musq2.x, mu2sq = musq2.y;
        float mu12  = mu1_ * mu2_;
        float s1sq = fabsf(m11 - mu1sq);
        float s2sq = fabsf(m22 - mu2sq);
        float s12  = m12 - mu12;
        float num = (2.f*mu12 + SSIM_C1) * (2.f*s12 + SSIM_C2);
        float den = (mu1sq + mu2sq + SSIM_C1) * (s1sq + s2sq + SSIM_C2);
        float v = __fdividef(num, den);
        acc[j] += fminf(1.f, fmaxf(-1.f, v));
    }
    __syncthreads();
}

__global__ __launch_bounds__(NT, 4)
void mssim_kernel(const float* __restrict__ b1,
                  const float* __restrict__ b2,
                  float* __restrict__ out)
{
    __shared__ float2 sT [S * S];      // interleaved (v1,v2): 18432 B
    __shared__ float2 Hmu[S * 32];     // 12288 B
    __shared__ float2 Hm [S * 32];     // 12288 B
    __shared__ float  Hc [S * 32];     //  6144 B   -> 49152 B total

    const int tid = threadIdx.x;
    const int plane = blockIdx.z;
    const long base = (long)plane * (512 * 512);
    const int ox = blockIdx.x * TILE - RAD;
    const int oy = blockIdx.y * TILE - RAD;

    #pragma unroll
    for (int sIt = 0; sIt < 9; ++sIt) {
        int i  = tid + NT * sIt;               // 0..2303
        int ly = i / S;
        int lx = i - ly * S;
        int gy = oy + ly;
        int gx = ox + lx;
        float v1 = 0.f, v2 = 0.f;
        if (gy >= 0 && gy < 512 && gx >= 0 && gx < 512) {
            long idx = base + (long)gy * 512 + gx;
            v1 = b1[idx];
            v2 = b2[idx];
        }
        sT[i] = make_float2(v1, v2);           // STS.64
    }
    __syncthreads();

    float acc[4] = {0.f, 0.f, 0.f, 0.f};
    wpass<2>(sT, Hmu, Hm, Hc, tid, acc);
    wpass<5>(sT, Hmu, Hm, Hc, tid, acc);
    wpass<8>(sT, Hmu, Hm, Hc, tid, acc);

    const int tx = tid & 31;
    const int ty = tid >> 5;
    const int gx = blockIdx.x * TILE + tx;
    #pragma unroll
    for (int j = 0; j < 4; ++j) {
        int gy = blockIdx.y * TILE + ty * 4 + j;
        out[base + (long)gy * 512 + gx] = 0.25f + acc[j] * (1.0f / 12.0f);
    }
}

extern "C" void kernel_launch(void* const* d_in, const int* in_sizes, int n_in,
                              void* d_out, int out_size) {
    const float* b1 = (const float*)d_in[0];
    const float* b2 = (const float*)d_in[1];

    // build packed 1D factors on device, then stage -> __constant__
    prep_weights<<<1, 32>>>((const float*)d_in[2], (const float*)d_in[3],
                            (const float*)d_in[4]);
    void* stage_ptr = nullptr;
    cudaGetSymbolAddress(&stage_ptr, g_stage);
    cudaMemcpyToSymbolAsync(c_w, stage_ptr, sizeof(Weights), 0,
                            cudaMemcpyDeviceToDevice, 0);

    dim3 grid(512 / TILE, 512 / TILE, 96);
    mssim_kernel<<<grid, NT>>>(b1, b2, (float*)d_out);
}

// round 9
// speedup vs baseline: 2.2632x; 1.8390x over previous
#include <cuda_runtime.h>

// MS-SSIM (windows 5/11/17), fused separable, f32x2-packed, dense-LDS version.
// out = 0.25 + sum_k clip(ssim_k, -1, 1) / 12

#define TILE 32
#define RAD 8
#define S 48
#define NT 256
#define SSIM_C1 (0.01f*0.01f)
#define SSIM_C2 (0.03f*0.03f)

struct Weights {
    float2 h5[5],  v5[5];
    float2 h11[11], v11[11];
    float2 h17[17], v17[17];
};
__device__  Weights g_stage;
__constant__ Weights c_w;

union F2U { float2 f; unsigned long long u; };

__device__ __forceinline__ float2 ffma2(float2 a, float2 b, float2 c) {
    F2U A, B, C, D; A.f = a; B.f = b; C.f = c;
    asm("fma.rn.f32x2 %0, %1, %2, %3;" : "=l"(D.u) : "l"(A.u), "l"(B.u), "l"(C.u));
    return D.f;
}
__device__ __forceinline__ float2 fmul2(float2 a, float2 b) {
    F2U A, B, D; A.f = a; B.f = b;
    asm("mul.rn.f32x2 %0, %1, %2;" : "=l"(D.u) : "l"(A.u), "l"(B.u));
    return D.f;
}

__global__ void prep_weights(const float* g5, const float* g11, const float* g17) {
    if (threadIdx.x != 0) return;
    #pragma unroll
    for (int t = 0; t < 5; ++t) {
        float h = g5[2*5 + t];
        float v = g5[t*5 + 2] / g5[2*5 + 2];
        g_stage.h5[t] = make_float2(h, h);
        g_stage.v5[t] = make_float2(v, v);
    }
    #pragma unroll
    for (int t = 0; t < 11; ++t) {
        float h = g11[5*11 + t];
        float v = g11[t*11 + 5] / g11[5*11 + 5];
        g_stage.h11[t] = make_float2(h, h);
        g_stage.v11[t] = make_float2(v, v);
    }
    #pragma unroll
    for (int t = 0; t < 17; ++t) {
        float h = g17[8*17 + t];
        float v = g17[t*17 + 8] / g17[8*17 + 8];
        g_stage.h17[t] = make_float2(h, h);
        g_stage.v17[t] = make_float2(v, v);
    }
}

template<int R>
__device__ __forceinline__ void wpass(const float4* __restrict__ sT4,
                                      float2* __restrict__ Hmu,
                                      float2* __restrict__ Hm,
                                      float*  __restrict__ Hc,
                                      int tid, float acc[4])
{
    constexpr int K    = 2*R + 1;
    constexpr int ROWS = 32 + 2*R;           // H rows actually needed
    constexpr int R0   = RAD - R;            // first H row
    constexpr int NI   = ROWS * 16;          // items: (row, col-pair)
    constexpr int ODD  = (R & 1);
    constexpr int L    = (K + 1 + ODD + 1) / 2;  // float4 loads per item: 3/7/9

    const float2* wh = (R == 2) ? c_w.h5 : (R == 5) ? c_w.h11 : c_w.h17;
    const float2* wv = (R == 2) ? c_w.v5 : (R == 5) ? c_w.v11 : c_w.v17;

    // ---- horizontal pass: dense float4 sliding loads, 2 output cols/thread ----
    #pragma unroll
    for (int it = 0; it < 3; ++it) {
        int i = tid + NT * it;
        if (i < NI) {
            int row = R0 + (i >> 4);
            int cg  = i & 15;                          // output cols (2cg, 2cg+1)
            // even-aligned pixel start: s0 = 2cg + RAD - R - ODD
            const float4* p4 = sT4 + ((row * S + 2*cg + RAD - R - ODD) >> 1);
            float2 mu0 = {0,0}, mu1 = {0,0}, mm0 = {0,0}, mm1 = {0,0};
            float  c0a = 0.f, c1a = 0.f;

            auto tap = [&](float2 v, int t0) {
                if (t0 >= 0 && t0 <= K) {              // compile-time after unroll
                    float2 p2 = fmul2(v, v);
                    float  pc = v.x * v.y;
                    if (t0 < K) {
                        float2 w = wh[t0];
                        mu0 = ffma2(w, v,  mu0);
                        mm0 = ffma2(w, p2, mm0);
                        c0a = fmaf(w.x, pc, c0a);
                    }
                    if (t0 >= 1) {
                        float2 w = wh[t0 - 1];
                        mu1 = ffma2(w, v,  mu1);
                        mm1 = ffma2(w, p2, mm1);
                        c1a = fmaf(w.x, pc, c1a);
                    }
                }
            };

            #pragma unroll
            for (int l = 0; l < L; ++l) {
                float4 q = p4[l];                      // LDS.128, dense across lanes
                tap(make_float2(q.x, q.y), 2*l - ODD);
                tap(make_float2(q.z, q.w), 2*l - ODD + 1);
            }

            int o = row * 32 + 2*cg;
            *reinterpret_cast<float4*>(Hmu + o) = make_float4(mu0.x, mu0.y, mu1.x, mu1.y);
            *reinterpret_cast<float4*>(Hm  + o) = make_float4(mm0.x, mm0.y, mm1.x, mm1.y);
            *reinterpret_cast<float2*>(Hc  + o) = make_float2(c0a, c1a);
        }
    }
    __syncthreads();

    // ---- vertical pass: 1 col x 4 rows per thread (dense stride-1 loads) ----
    const int col = tid & 31;
    const int ty  = tid >> 5;
    float2 amu[4] = {}; float2 am[4] = {}; float ac[4] = {0,0,0,0};
    const int ybase = RAD + 4*ty - R;
    #pragma unroll
    for (int yy = 0; yy < 4 + 2*R; ++yy) {
        int o = (ybase + yy) * 32 + col;
        float2 hmu = Hmu[o];
        float2 hm  = Hm[o];
        float  hc  = Hc[o];
        #pragma unroll
        for (int j = 0; j < 4; ++j) {
            int t = yy - j;
            if (t >= 0 && t < K) {
                float2 wp = wv[t];
                amu[j] = ffma2(wp, hmu, amu[j]);
                am[j]  = ffma2(wp, hm,  am[j]);
                ac[j]  = fmaf(wp.x, hc, ac[j]);
            }
        }
    }

    #pragma unroll
    for (int j = 0; j < 4; ++j) {
        float2 musq2 = fmul2(amu[j], amu[j]);
        float mu1sq = musq2.x, mu2sq = musq2.y;
        float mu12  = amu[j].x * amu[j].y;
        float s1sq = fabsf(am[j].x - mu1sq);
        float s2sq = fabsf(am[j].y - mu2sq);
        float s12  = ac[j] - mu12;
        float num = (2.f*mu12 + SSIM_C1) * (2.f*s12 + SSIM_C2);
        float den = (mu1sq + mu2sq + SSIM_C1) * (s1sq + s2sq + SSIM_C2);
        float v = __fdividef(num, den);
        acc[j] += fminf(1.f, fmaxf(-1.f, v));
    }
    __syncthreads();   // H reused by next window
}

__global__ __launch_bounds__(NT)
void mssim_kernel(const float* __restrict__ b1,
                  const float* __restrict__ b2,
                  float* __restrict__ out)
{
    // 49152 B total, all regions 16B-aligned
    __shared__ __align__(16) char smbuf[49152];
    float2* sT  = reinterpret_cast<float2*>(smbuf);            // 48*48*8  = 18432
    float2* Hmu = reinterpret_cast<float2*>(smbuf + 18432);    // 48*32*8  = 12288
    float2* Hm  = reinterpret_cast<float2*>(smbuf + 30720);    // 48*32*8  = 12288
    float*  Hc  = reinterpret_cast<float*> (smbuf + 43008);    // 48*32*4  =  6144

    const int tid = threadIdx.x;
    const int plane = blockIdx.z;
    const long base = (long)plane * (512 * 512);
    const int ox = blockIdx.x * TILE - RAD;
    const int oy = blockIdx.y * TILE - RAD;

    #pragma unroll
    for (int sIt = 0; sIt < 9; ++sIt) {
        int i  = tid + NT * sIt;               // 0..2303
        int ly = i / S;
        int lx = i - ly * S;
        int gy = oy + ly;
        int gx = ox + lx;
        float v1 = 0.f, v2 = 0.f;
        if (gy >= 0 && gy < 512 && gx >= 0 && gx < 512) {
            long idx = base + (long)gy * 512 + gx;
            v1 = b1[idx];
            v2 = b2[idx];
        }
        sT[i] = make_float2(v1, v2);
    }
    __syncthreads();

    const float4* sT4 = reinterpret_cast<const float4*>(smbuf);

    float acc[4] = {0.f, 0.f, 0.f, 0.f};
    wpass<2>(sT4, Hmu, Hm, Hc, tid, acc);
    wpass<5>(sT4, Hmu, Hm, Hc, tid, acc);
    wpass<8>(sT4, Hmu, Hm, Hc, tid, acc);

    const int tx = tid & 31;
    const int ty = tid >> 5;
    const int gx = blockIdx.x * TILE + tx;
    #pragma unroll
    for (int j = 0; j < 4; ++j) {
        int gy = blockIdx.y * TILE + ty * 4 + j;
        out[base + (long)gy * 512 + gx] = 0.25f + acc[j] * (1.0f / 12.0f);
    }
}

extern "C" void kernel_launch(void* const* d_in, const int* in_sizes, int n_in,
                              void* d_out, int out_size) {
    const float* b1 = (const float*)d_in[0];
    const float* b2 = (const float*)d_in[1];

    prep_weights<<<1, 32>>>((const float*)d_in[2], (const float*)d_in[3],
                            (const float*)d_in[4]);
    void* stage_ptr = nullptr;
    cudaGetSymbolAddress(&stage_ptr, g_stage);
    cudaMemcpyToSymbolAsync(c_w, stage_ptr, sizeof(Weights), 0,
                            cudaMemcpyDeviceToDevice, 0);

    dim3 grid(512 / TILE, 512 / TILE, 96);
    mssim_kernel<<<grid, NT>>>(b1, b2, (float*)d_out);
}

// round 10
// speedup vs baseline: 2.3468x; 1.0370x over previous
#include <cuda_runtime.h>

// MS-SSIM (windows 5/11/17), fused separable, f32x2-packed, 32x64 tile.
// out = 0.25 + sum_k clip(ssim_k, -1, 1) / 12

#define RAD 8
#define S 48            // smem tile cols: 32 + 2*RAD
#define TR 80           // smem tile rows: 64 + 2*RAD
#define NT 512
#define SSIM_C1 (0.01f*0.01f)
#define SSIM_C2 (0.03f*0.03f)

struct Weights {
    // dup pairs (w,w) for mu/mm; shifted pairs (w[t], w[t-1]) for cross term
    float2 h5[5],  hp5[7],  v5[5],  vp5[7];
    float2 h11[11], hp11[13], v11[11], vp11[13];
    float2 h17[17], hp17[19], v17[17], vp17[19];
};
__device__  Weights g_stage;
__constant__ Weights c_w;

union F2U { float2 f; unsigned long long u; };

__device__ __forceinline__ float2 ffma2(float2 a, float2 b, float2 c) {
    F2U A, B, C, D; A.f = a; B.f = b; C.f = c;
    asm("fma.rn.f32x2 %0, %1, %2, %3;" : "=l"(D.u) : "l"(A.u), "l"(B.u), "l"(C.u));
    return D.f;
}
__device__ __forceinline__ float2 fmul2(float2 a, float2 b) {
    F2U A, B, D; A.f = a; B.f = b;
    asm("mul.rn.f32x2 %0, %1, %2;" : "=l"(D.u) : "l"(A.u), "l"(B.u));
    return D.f;
}

__device__ __forceinline__ void build_tables(const float* g, int R,
                                             float2* h, float2* hp,
                                             float2* v, float2* vp) {
    const int K = 2*R + 1;
    float hv[17], vv[17];
    float ctr = g[R*K + R];
    for (int t = 0; t < K; ++t) {
        hv[t] = g[R*K + t];
        vv[t] = g[t*K + R] / ctr;
    }
    for (int t = 0; t < K; ++t) {
        h[t] = make_float2(hv[t], hv[t]);
        v[t] = make_float2(vv[t], vv[t]);
    }
    for (int t = 0; t <= K + 1; ++t) {   // pair tables, zero-padded
        float a = (t <= K-1) ? hv[t] : 0.f;
        float b = (t >= 1 && t <= K) ? hv[t-1] : 0.f;
        hp[t] = make_float2(a, b);
        float c = (t <= K-1) ? vv[t] : 0.f;
        float d = (t >= 1 && t <= K) ? vv[t-1] : 0.f;
        vp[t] = make_float2(c, d);
    }
}

__global__ void prep_weights(const float* g5, const float* g11, const float* g17) {
    if (threadIdx.x != 0) return;
    build_tables(g5,  2, g_stage.h5,  g_stage.hp5,  g_stage.v5,  g_stage.vp5);
    build_tables(g11, 5, g_stage.h11, g_stage.hp11, g_stage.v11, g_stage.vp11);
    build_tables(g17, 8, g_stage.h17, g_stage.hp17, g_stage.v17, g_stage.vp17);
}

template<int R>
__device__ __forceinline__ void wpass(const float4* __restrict__ sT4,
                                      float2* __restrict__ Hmu,
                                      float2* __restrict__ Hm,
                                      float*  __restrict__ Hc,
                                      int tid, float acc[4])
{
    constexpr int K    = 2*R + 1;          // taps, indices 0..2R
    constexpr int ROWS = 64 + 2*R;         // H rows needed
    constexpr int R0   = RAD - R;
    constexpr int NI   = ROWS * 16;
    constexpr int ODD  = ((RAD - R) & 1);
    constexpr int L    = (2*R + 2 + ODD + 1) / 2;   // float4 loads/item

    const float2* wh = (R == 2) ? c_w.h5  : (R == 5) ? c_w.h11  : c_w.h17;
    const float2* hp = (R == 2) ? c_w.hp5 : (R == 5) ? c_w.hp11 : c_w.hp17;
    const float2* wv = (R == 2) ? c_w.v5  : (R == 5) ? c_w.v11  : c_w.v17;
    const float2* vp = (R == 2) ? c_w.vp5 : (R == 5) ? c_w.vp11 : c_w.vp17;

    // ---- horizontal: 2 output cols/item, dense float4 sliding loads ----
    #pragma unroll
    for (int it = 0; it < 3; ++it) {
        int i = tid + NT * it;
        if (i < NI) {
            int row = R0 + (i >> 4);
            int cg  = i & 15;
            const float4* p4 = sT4 + ((row * S + 2*cg + RAD - R - ODD) >> 1);
            float2 mu0 = {0,0}, mu1 = {0,0}, mm0 = {0,0}, mm1 = {0,0};
            float2 c01 = {0,0};

            auto tap = [&](float2 v, int t0) {
                if (t0 >= 0 && t0 <= K) {            // compile-time after unroll
                    float2 p2 = fmul2(v, v);
                    float  pc = v.x * v.y;
                    float2 pcd = make_float2(pc, pc);
                    if (t0 < K) {
                        float2 w = wh[t0];
                        mu0 = ffma2(w, v,  mu0);
                        mm0 = ffma2(w, p2, mm0);
                    }
                    if (t0 >= 1) {
                        float2 w = wh[t0 - 1];
                        mu1 = ffma2(w, v,  mu1);
                        mm1 = ffma2(w, p2, mm1);
                    }
                    c01 = ffma2(hp[t0], pcd, c01);   // (c0, c1) pair
                }
            };

            #pragma unroll
            for (int l = 0; l < L; ++l) {
                float4 q = p4[l];                    // LDS.128, dense
                tap(make_float2(q.x, q.y), 2*l - ODD);
                tap(make_float2(q.z, q.w), 2*l - ODD + 1);
            }

            int o = row * 32 + 2*cg;
            *reinterpret_cast<float4*>(Hmu + o) = make_float4(mu0.x, mu0.y, mu1.x, mu1.y);
            *reinterpret_cast<float4*>(Hm  + o) = make_float4(mm0.x, mm0.y, mm1.x, mm1.y);
            *reinterpret_cast<float2*>(Hc  + o) = c01;
        }
    }
    __syncthreads();

    // ---- vertical: 1 col x 4 rows per thread, cross term tap-pair packed ----
    const int col = tid & 31;
    const int ty  = tid >> 5;                        // 0..15 -> rows 4ty..4ty+3
    float2 amu[4] = {}; float2 am[4] = {};
    float2 ac01 = {0,0}, ac23 = {0,0};
    const int ybase = RAD + 4*ty - R;
    #pragma unroll
    for (int yy = 0; yy < 4 + 2*R; ++yy) {
        int o = (ybase + yy) * 32 + col;
        float2 hmu = Hmu[o];
        float2 hm  = Hm[o];
        float  hc  = Hc[o];
        float2 hcd = make_float2(hc, hc);
        if (yy <= 2*R + 1)                ac01 = ffma2(vp[yy],     hcd, ac01);
        if (yy >= 2 && yy <= 2*R + 3)     ac23 = ffma2(vp[yy - 2], hcd, ac23);
        #pragma unroll
        for (int j = 0; j < 4; ++j) {
            int t = yy - j;
            if (t >= 0 && t < K) {
                float2 wp = wv[t];
                amu[j] = ffma2(wp, hmu, amu[j]);
                am[j]  = ffma2(wp, hm,  am[j]);
            }
        }
    }

    float acv[4] = { ac01.x, ac01.y, ac23.x, ac23.y };
    #pragma unroll
    for (int j = 0; j < 4; ++j) {
        float2 musq2 = fmul2(amu[j], amu[j]);
        float mu1sq = musq2.x, mu2sq = musq2.y;
        float mu12  = amu[j].x * amu[j].y;
        float s1sq = fabsf(am[j].x - mu1sq);
        float s2sq = fabsf(am[j].y - mu2sq);
        float s12  = acv[j] - mu12;
        float num = (2.f*mu12 + SSIM_C1) * (2.f*s12 + SSIM_C2);
        float den = (mu1sq + mu2sq + SSIM_C1) * (s1sq + s2sq + SSIM_C2);
        float v = __fdividef(num, den);
        acc[j] += fminf(1.f, fmaxf(-1.f, v));
    }
    __syncthreads();   // H reused by next window
}

__global__ __launch_bounds__(NT, 2)
void mssim_kernel(const float* __restrict__ b1,
                  const float* __restrict__ b2,
                  float* __restrict__ out)
{
    // dynamic smem: sT 30720 | Hmu 20480 | Hm 20480 | Hc 10240  = 81920 B
    extern __shared__ __align__(16) char smbuf[];
    float2* sT  = reinterpret_cast<float2*>(smbuf);
    float2* Hmu = reinterpret_cast<float2*>(smbuf + 30720);
    float2* Hm  = reinterpret_cast<float2*>(smbuf + 51200);
    float*  Hc  = reinterpret_cast<float*> (smbuf + 71680);

    const int tid = threadIdx.x;
    const int plane = blockIdx.z;
    const long base = (long)plane * (512 * 512);
    const int ox = blockIdx.x * 32 - RAD;
    const int oy = blockIdx.y * 64 - RAD;

    #pragma unroll
    for (int sIt = 0; sIt < 8; ++sIt) {
        int i = tid + NT * sIt;                // 0..4095, need 0..3839
        if (i < TR * S) {
            int ly = i / S;
            int lx = i - ly * S;
            int gy = oy + ly;
            int gx = ox + lx;
            float v1 = 0.f, v2 = 0.f;
            if (gy >= 0 && gy < 512 && gx >= 0 && gx < 512) {
                long idx = base + (long)gy * 512 + gx;
                v1 = b1[idx];
                v2 = b2[idx];
            }
            sT[i] = make_float2(v1, v2);
        }
    }
    __syncthreads();

    const float4* sT4 = reinterpret_cast<const float4*>(smbuf);

    float acc[4] = {0.f, 0.f, 0.f, 0.f};
    wpass<2>(sT4, Hmu, Hm, Hc, tid, acc);
    wpass<5>(sT4, Hmu, Hm, Hc, tid, acc);
    wpass<8>(sT4, Hmu, Hm, Hc, tid, acc);

    const int tx = tid & 31;
    const int ty = tid >> 5;
    const int gx = blockIdx.x * 32 + tx;
    #pragma unroll
    for (int j = 0; j < 4; ++j) {
        int gy = blockIdx.y * 64 + ty * 4 + j;
        out[base + (long)gy * 512 + gx] = 0.25f + acc[j] * (1.0f / 12.0f);
    }
}

extern "C" void kernel_launch(void* const* d_in, const int* in_sizes, int n_in,
                              void* d_out, int out_size) {
    const float* b1 = (const float*)d_in[0];
    const float* b2 = (const float*)d_in[1];

    prep_weights<<<1, 32>>>((const float*)d_in[2], (const float*)d_in[3],
                            (const float*)d_in[4]);
    void* stage_ptr = nullptr;
    cudaGetSymbolAddress(&stage_ptr, g_stage);
    cudaMemcpyToSymbolAsync(c_w, stage_ptr, sizeof(Weights), 0,
                            cudaMemcpyDeviceToDevice, 0);

    static bool attr_set = false;
    if (!attr_set) {
        cudaFuncSetAttribute(mssim_kernel,
                             cudaFuncAttributeMaxDynamicSharedMemorySize, 81920);
        attr_set = true;
    }

    dim3 grid(512 / 32, 512 / 64, 96);     // 16 x 8 x 96
    mssim_kernel<<<grid, NT, 81920>>>(b1, b2, (float*)d_out);
}